// round 1
// baseline (speedup 1.0000x reference)
#include <cuda_runtime.h>

#define NBINS 128
#define OUT_DIMS 4

__global__ __launch_bounds__(256)
void grid_encoding3d_kernel(const float* __restrict__ x,
                            const float4* __restrict__ grid,
                            float4* __restrict__ out,
                            int n)
{
    int i = blockIdx.x * blockDim.x + threadIdx.x;
    if (i >= n) return;

    // Load point coords (3 scalar loads; warp-contiguous stream)
    float px = x[3 * i + 0];
    float py = x[3 * i + 1];
    float pz = x[3 * i + 2];

    // p = clip(x * NBINS, 0, NBINS-1)
    px = fminf(fmaxf(px * (float)NBINS, 0.0f), (float)(NBINS - 1));
    py = fminf(fmaxf(py * (float)NBINS, 0.0f), (float)(NBINS - 1));
    pz = fminf(fmaxf(pz * (float)NBINS, 0.0f), (float)(NBINS - 1));

    int ix0 = (int)floorf(px);
    int iy0 = (int)floorf(py);
    int iz0 = (int)floorf(pz);

    float fx = px - (float)ix0;
    float fy = py - (float)iy0;
    float fz = pz - (float)iz0;

    int ix1 = min(ix0 + 1, NBINS - 1);
    int iy1 = min(iy0 + 1, NBINS - 1);
    int iz1 = min(iz0 + 1, NBINS - 1);

    // Row bases: grid[ix][iy][*] flattened in float4 units
    int b00 = (ix0 * NBINS + iy0) * NBINS;
    int b01 = (ix0 * NBINS + iy1) * NBINS;
    int b10 = (ix1 * NBINS + iy0) * NBINS;
    int b11 = (ix1 * NBINS + iy1) * NBINS;

    // Issue all 8 gathers back-to-back (MLP=8) before dependent math.
    float4 c000 = __ldg(&grid[b00 + iz0]);
    float4 c001 = __ldg(&grid[b00 + iz1]);
    float4 c010 = __ldg(&grid[b01 + iz0]);
    float4 c011 = __ldg(&grid[b01 + iz1]);
    float4 c100 = __ldg(&grid[b10 + iz0]);
    float4 c101 = __ldg(&grid[b10 + iz1]);
    float4 c110 = __ldg(&grid[b11 + iz0]);
    float4 c111 = __ldg(&grid[b11 + iz1]);

    float wx1 = fx, wx0 = 1.0f - fx;
    float wy1 = fy, wy0 = 1.0f - fy;
    float wz1 = fz, wz0 = 1.0f - fz;

    float w000 = wx0 * wy0 * wz0;
    float w001 = wx0 * wy0 * wz1;
    float w010 = wx0 * wy1 * wz0;
    float w011 = wx0 * wy1 * wz1;
    float w100 = wx1 * wy0 * wz0;
    float w101 = wx1 * wy0 * wz1;
    float w110 = wx1 * wy1 * wz0;
    float w111 = wx1 * wy1 * wz1;

    float4 acc;
    acc.x = w000 * c000.x;
    acc.y = w000 * c000.y;
    acc.z = w000 * c000.z;
    acc.w = w000 * c000.w;

    acc.x = fmaf(w001, c001.x, acc.x);
    acc.y = fmaf(w001, c001.y, acc.y);
    acc.z = fmaf(w001, c001.z, acc.z);
    acc.w = fmaf(w001, c001.w, acc.w);

    acc.x = fmaf(w010, c010.x, acc.x);
    acc.y = fmaf(w010, c010.y, acc.y);
    acc.z = fmaf(w010, c010.z, acc.z);
    acc.w = fmaf(w010, c010.w, acc.w);

    acc.x = fmaf(w011, c011.x, acc.x);
    acc.y = fmaf(w011, c011.y, acc.y);
    acc.z = fmaf(w011, c011.z, acc.z);
    acc.w = fmaf(w011, c011.w, acc.w);

    acc.x = fmaf(w100, c100.x, acc.x);
    acc.y = fmaf(w100, c100.y, acc.y);
    acc.z = fmaf(w100, c100.z, acc.z);
    acc.w = fmaf(w100, c100.w, acc.w);

    acc.x = fmaf(w101, c101.x, acc.x);
    acc.y = fmaf(w101, c101.y, acc.y);
    acc.z = fmaf(w101, c101.z, acc.z);
    acc.w = fmaf(w101, c101.w, acc.w);

    acc.x = fmaf(w110, c110.x, acc.x);
    acc.y = fmaf(w110, c110.y, acc.y);
    acc.z = fmaf(w110, c110.z, acc.z);
    acc.w = fmaf(w110, c110.w, acc.w);

    acc.x = fmaf(w111, c111.x, acc.x);
    acc.y = fmaf(w111, c111.y, acc.y);
    acc.z = fmaf(w111, c111.z, acc.z);
    acc.w = fmaf(w111, c111.w, acc.w);

    out[i] = acc;  // coalesced STG.128
}

extern "C" void kernel_launch(void* const* d_in, const int* in_sizes, int n_in,
                              void* d_out, int out_size)
{
    const float*  x    = (const float*)d_in[0];   // [N,3] float32
    const float4* grid = (const float4*)d_in[1];  // [128,128,128,4] float32
    float4*       out  = (float4*)d_out;          // [N,4] float32

    int n = in_sizes[0] / 3;

    const int block = 256;
    int grid_dim = (n + block - 1) / block;
    grid_encoding3d_kernel<<<grid_dim, block>>>(x, grid, out, n);
}

// round 2
// speedup vs baseline: 1.0457x; 1.0457x over previous
#include <cuda_runtime.h>
#include <cuda_fp16.h>

#define NB 128
#define NB3 (NB * NB * NB)

// Pair table: entry[ix][iy][iz] = { grid[ix][iy][iz] (4 x fp16), grid[ix][iy][min(iz+1,127)] (4 x fp16) }
// 16 bytes per entry, 33.5 MB total — L2-resident.
__device__ uint4 g_pairs[NB3];

__global__ __launch_bounds__(256)
void build_pairs_kernel(const float4* __restrict__ grid)
{
    int idx = blockIdx.x * blockDim.x + threadIdx.x;
    if (idx >= NB3) return;

    int iz = idx & (NB - 1);
    float4 a = grid[idx];
    float4 b = grid[(iz == NB - 1) ? idx : idx + 1];

    __half2 h0 = __floats2half2_rn(a.x, a.y);
    __half2 h1 = __floats2half2_rn(a.z, a.w);
    __half2 h2 = __floats2half2_rn(b.x, b.y);
    __half2 h3 = __floats2half2_rn(b.z, b.w);

    uint4 v;
    v.x = *reinterpret_cast<const unsigned int*>(&h0);
    v.y = *reinterpret_cast<const unsigned int*>(&h1);
    v.z = *reinterpret_cast<const unsigned int*>(&h2);
    v.w = *reinterpret_cast<const unsigned int*>(&h3);
    g_pairs[idx] = v;
}

// z-lerp of one packed pair: returns corner_a*wz0 + corner_b*wz1 as float4
__device__ __forceinline__ float4 zlerp(uint4 p, float wz0, float wz1)
{
    __half2 h0 = *reinterpret_cast<const __half2*>(&p.x);
    __half2 h1 = *reinterpret_cast<const __half2*>(&p.y);
    __half2 h2 = *reinterpret_cast<const __half2*>(&p.z);
    __half2 h3 = *reinterpret_cast<const __half2*>(&p.w);

    float2 axy = __half22float2(h0);
    float2 azw = __half22float2(h1);
    float2 bxy = __half22float2(h2);
    float2 bzw = __half22float2(h3);

    float4 r;
    r.x = fmaf(wz1, bxy.x, wz0 * axy.x);
    r.y = fmaf(wz1, bxy.y, wz0 * axy.y);
    r.z = fmaf(wz1, bzw.x, wz0 * azw.x);
    r.w = fmaf(wz1, bzw.y, wz0 * azw.y);
    return r;
}

__global__ __launch_bounds__(256)
void interp_kernel(const float* __restrict__ x,
                   float4* __restrict__ out,
                   int n)
{
    int i = blockIdx.x * blockDim.x + threadIdx.x;
    if (i >= n) return;

    float px = x[3 * i + 0];
    float py = x[3 * i + 1];
    float pz = x[3 * i + 2];

    px = fminf(fmaxf(px * (float)NB, 0.0f), (float)(NB - 1));
    py = fminf(fmaxf(py * (float)NB, 0.0f), (float)(NB - 1));
    pz = fminf(fmaxf(pz * (float)NB, 0.0f), (float)(NB - 1));

    int ix0 = (int)floorf(px);
    int iy0 = (int)floorf(py);
    int iz0 = (int)floorf(pz);

    float fx = px - (float)ix0;
    float fy = py - (float)iy0;
    float fz = pz - (float)iz0;

    int ix1 = min(ix0 + 1, NB - 1);
    int iy1 = min(iy0 + 1, NB - 1);

    int b00 = (ix0 * NB + iy0) * NB + iz0;
    int b01 = (ix0 * NB + iy1) * NB + iz0;
    int b10 = (ix1 * NB + iy0) * NB + iz0;
    int b11 = (ix1 * NB + iy1) * NB + iz0;

    // 4 scattered LDG.128, issued back-to-back (MLP=4), each carrying a full z-pair.
    uint4 p00 = __ldg(&g_pairs[b00]);
    uint4 p01 = __ldg(&g_pairs[b01]);
    uint4 p10 = __ldg(&g_pairs[b10]);
    uint4 p11 = __ldg(&g_pairs[b11]);

    float wz1 = fz, wz0 = 1.0f - fz;
    float wx1 = fx, wx0 = 1.0f - fx;
    float wy1 = fy, wy0 = 1.0f - fy;

    float4 m00 = zlerp(p00, wz0, wz1);
    float4 m01 = zlerp(p01, wz0, wz1);
    float4 m10 = zlerp(p10, wz0, wz1);
    float4 m11 = zlerp(p11, wz0, wz1);

    float w00 = wx0 * wy0;
    float w01 = wx0 * wy1;
    float w10 = wx1 * wy0;
    float w11 = wx1 * wy1;

    float4 acc;
    acc.x = w00 * m00.x;
    acc.y = w00 * m00.y;
    acc.z = w00 * m00.z;
    acc.w = w00 * m00.w;

    acc.x = fmaf(w01, m01.x, acc.x);
    acc.y = fmaf(w01, m01.y, acc.y);
    acc.z = fmaf(w01, m01.z, acc.z);
    acc.w = fmaf(w01, m01.w, acc.w);

    acc.x = fmaf(w10, m10.x, acc.x);
    acc.y = fmaf(w10, m10.y, acc.y);
    acc.z = fmaf(w10, m10.z, acc.z);
    acc.w = fmaf(w10, m10.w, acc.w);

    acc.x = fmaf(w11, m11.x, acc.x);
    acc.y = fmaf(w11, m11.y, acc.y);
    acc.z = fmaf(w11, m11.z, acc.z);
    acc.w = fmaf(w11, m11.w, acc.w);

    out[i] = acc;
}

extern "C" void kernel_launch(void* const* d_in, const int* in_sizes, int n_in,
                              void* d_out, int out_size)
{
    const float*  x    = (const float*)d_in[0];   // [N,3] float32
    const float4* grid = (const float4*)d_in[1];  // [128,128,128,4] float32
    float4*       out  = (float4*)d_out;          // [N,4] float32

    int n = in_sizes[0] / 3;

    const int block = 256;
    build_pairs_kernel<<<(NB3 + block - 1) / block, block>>>(grid);
    interp_kernel<<<(n + block - 1) / block, block>>>(x, out, n);
}

// round 3
// speedup vs baseline: 1.0915x; 1.0437x over previous
#include <cuda_runtime.h>
#include <cuda_fp16.h>

#define NB 128
#define NB3 (NB * NB * NB)

// Pair table: entry[ix][iy][iz] = { grid[ix][iy][iz] (4 x fp16), grid[ix][iy][min(iz+1,127)] (4 x fp16) }
__device__ uint4 g_pairs[NB3];

__global__ __launch_bounds__(256)
void build_pairs_kernel(const float4* __restrict__ grid)
{
    int idx = blockIdx.x * blockDim.x + threadIdx.x;
    if (idx >= NB3) return;

    int iz = idx & (NB - 1);
    float4 a = grid[idx];
    float4 b = grid[(iz == NB - 1) ? idx : idx + 1];

    __half2 h0 = __floats2half2_rn(a.x, a.y);
    __half2 h1 = __floats2half2_rn(a.z, a.w);
    __half2 h2 = __floats2half2_rn(b.x, b.y);
    __half2 h3 = __floats2half2_rn(b.z, b.w);

    uint4 v;
    v.x = *reinterpret_cast<const unsigned int*>(&h0);
    v.y = *reinterpret_cast<const unsigned int*>(&h1);
    v.z = *reinterpret_cast<const unsigned int*>(&h2);
    v.w = *reinterpret_cast<const unsigned int*>(&h3);
    g_pairs[idx] = v;
}

// z-lerp of one packed pair: corner_a*wz0 + corner_b*wz1
__device__ __forceinline__ float4 zlerp(uint4 p, float wz0, float wz1)
{
    float2 axy = __half22float2(*reinterpret_cast<const __half2*>(&p.x));
    float2 azw = __half22float2(*reinterpret_cast<const __half2*>(&p.y));
    float2 bxy = __half22float2(*reinterpret_cast<const __half2*>(&p.z));
    float2 bzw = __half22float2(*reinterpret_cast<const __half2*>(&p.w));

    float4 r;
    r.x = fmaf(wz1, bxy.x, wz0 * axy.x);
    r.y = fmaf(wz1, bxy.y, wz0 * axy.y);
    r.z = fmaf(wz1, bzw.x, wz0 * azw.x);
    r.w = fmaf(wz1, bzw.y, wz0 * azw.y);
    return r;
}

struct PointIdx {
    int b00, b01, b10, b11;
    float fx, fy, fz;
};

__device__ __forceinline__ PointIdx make_idx(float px, float py, float pz)
{
    px = fminf(fmaxf(px * (float)NB, 0.0f), (float)(NB - 1));
    py = fminf(fmaxf(py * (float)NB, 0.0f), (float)(NB - 1));
    pz = fminf(fmaxf(pz * (float)NB, 0.0f), (float)(NB - 1));

    int ix0 = (int)floorf(px);
    int iy0 = (int)floorf(py);
    int iz0 = (int)floorf(pz);

    PointIdx r;
    r.fx = px - (float)ix0;
    r.fy = py - (float)iy0;
    r.fz = pz - (float)iz0;   // pair table handles iz edge (b=a at iz=127, fz=0)

    int ix1 = min(ix0 + 1, NB - 1);
    int iy1 = min(iy0 + 1, NB - 1);

    r.b00 = (ix0 * NB + iy0) * NB + iz0;
    r.b01 = (ix0 * NB + iy1) * NB + iz0;
    r.b10 = (ix1 * NB + iy0) * NB + iz0;
    r.b11 = (ix1 * NB + iy1) * NB + iz0;
    return r;
}

__device__ __forceinline__ float4 bilerp_xy(uint4 p00, uint4 p01, uint4 p10, uint4 p11,
                                            float fx, float fy, float fz)
{
    float wz1 = fz, wz0 = 1.0f - fz;
    float4 m00 = zlerp(p00, wz0, wz1);
    float4 m01 = zlerp(p01, wz0, wz1);
    float4 m10 = zlerp(p10, wz0, wz1);
    float4 m11 = zlerp(p11, wz0, wz1);

    float wx1 = fx, wx0 = 1.0f - fx;
    float wy1 = fy, wy0 = 1.0f - fy;
    float w00 = wx0 * wy0;
    float w01 = wx0 * wy1;
    float w10 = wx1 * wy0;
    float w11 = wx1 * wy1;

    float4 acc;
    acc.x = w00 * m00.x;
    acc.y = w00 * m00.y;
    acc.z = w00 * m00.z;
    acc.w = w00 * m00.w;
    acc.x = fmaf(w01, m01.x, acc.x);
    acc.y = fmaf(w01, m01.y, acc.y);
    acc.z = fmaf(w01, m01.z, acc.z);
    acc.w = fmaf(w01, m01.w, acc.w);
    acc.x = fmaf(w10, m10.x, acc.x);
    acc.y = fmaf(w10, m10.y, acc.y);
    acc.z = fmaf(w10, m10.z, acc.z);
    acc.w = fmaf(w10, m10.w, acc.w);
    acc.x = fmaf(w11, m11.x, acc.x);
    acc.y = fmaf(w11, m11.y, acc.y);
    acc.z = fmaf(w11, m11.z, acc.z);
    acc.w = fmaf(w11, m11.w, acc.w);
    return acc;
}

// Two points per thread: i and i+half, 8 gathers in flight per thread.
__global__ __launch_bounds__(256)
void interp2_kernel(const float* __restrict__ x,
                    float4* __restrict__ out,
                    int n, int half)
{
    int i = blockIdx.x * blockDim.x + threadIdx.x;
    if (i >= half) return;
    int j = i + half;

    float ax = x[3 * i + 0];
    float ay = x[3 * i + 1];
    float az = x[3 * i + 2];

    bool hasB = (j < n);
    float bx = 0.0f, by = 0.0f, bz = 0.0f;
    if (hasB) {
        bx = x[3 * j + 0];
        by = x[3 * j + 1];
        bz = x[3 * j + 2];
    }

    PointIdx A = make_idx(ax, ay, az);
    PointIdx B = make_idx(bx, by, bz);

    // 8 scattered gathers issued back-to-back (MLP=8)
    uint4 a00 = __ldg(&g_pairs[A.b00]);
    uint4 a01 = __ldg(&g_pairs[A.b01]);
    uint4 a10 = __ldg(&g_pairs[A.b10]);
    uint4 a11 = __ldg(&g_pairs[A.b11]);
    uint4 b00 = __ldg(&g_pairs[B.b00]);
    uint4 b01 = __ldg(&g_pairs[B.b01]);
    uint4 b10 = __ldg(&g_pairs[B.b10]);
    uint4 b11 = __ldg(&g_pairs[B.b11]);

    out[i] = bilerp_xy(a00, a01, a10, a11, A.fx, A.fy, A.fz);
    if (hasB)
        out[j] = bilerp_xy(b00, b01, b10, b11, B.fx, B.fy, B.fz);
}

extern "C" void kernel_launch(void* const* d_in, const int* in_sizes, int n_in,
                              void* d_out, int out_size)
{
    const float*  x    = (const float*)d_in[0];   // [N,3] float32
    const float4* grid = (const float4*)d_in[1];  // [128,128,128,4] float32
    float4*       out  = (float4*)d_out;          // [N,4] float32

    int n = in_sizes[0] / 3;
    int half = (n + 1) / 2;

    const int block = 256;
    build_pairs_kernel<<<(NB3 + block - 1) / block, block>>>(grid);
    interp2_kernel<<<(half + block - 1) / block, block>>>(x, out, n, half);
}